// round 6
// baseline (speedup 1.0000x reference)
#include <cuda_runtime.h>
#include <math_constants.h>

#define B_  8
#define S_  2048
#define D_  512
#define H_  8
#define DH_ 64
#define M_  (B_*S_)   // 16384
#define NT_ (S_/64)   // 32 key tiles
#define QT_ 128       // q-rows per attention CTA

// Scratch (allocation-free rule: __device__ globals)
__device__ float g_Q[B_*H_*S_*DH_];
__device__ float g_K[B_*H_*S_*DH_];
__device__ float g_V[B_*H_*DH_*S_];   // TRANSPOSED: [B,H,Dh,S]
__device__ float g_O[M_*D_];
__device__ float g_X[M_*D_];
__device__ float g_Wi[3*D_*D_];
__device__ float g_Wo[D_*D_];

// ---------------------------------------------------------------------------
// helpers
// ---------------------------------------------------------------------------
__device__ __forceinline__ unsigned tf32u(float x) {
    unsigned u;
    asm("cvt.rna.tf32.f32 %0, %1;" : "=r"(u) : "f"(x));
    return u;
}
__device__ __forceinline__ float tf32f(float x) { return __uint_as_float(tf32u(x)); }
__device__ __forceinline__ unsigned fu(float x) { return __float_as_uint(x); }
__device__ __forceinline__ float ex2f(float x) {
    float y;
    asm("ex2.approx.f32 %0, %1;" : "=f"(y) : "f"(x));
    return y;
}

__device__ __forceinline__ void mma8(float* c, const unsigned* a, const unsigned* b) {
    asm volatile(
        "mma.sync.aligned.m16n8k8.row.col.f32.tf32.tf32.f32 "
        "{%0,%1,%2,%3}, {%4,%5,%6,%7}, {%8,%9}, {%0,%1,%2,%3};"
        : "+f"(c[0]), "+f"(c[1]), "+f"(c[2]), "+f"(c[3])
        : "r"(a[0]), "r"(a[1]), "r"(a[2]), "r"(a[3]), "r"(b[0]), "r"(b[1]));
}

__device__ __forceinline__ void ldsm4(unsigned* r, unsigned addr) {
    asm volatile("ldmatrix.sync.aligned.m8n8.x4.shared.b16 {%0,%1,%2,%3}, [%4];"
                 : "=r"(r[0]), "=r"(r[1]), "=r"(r[2]), "=r"(r[3]) : "r"(addr));
}

__device__ __forceinline__ unsigned sptr(const void* p) {
    return (unsigned)__cvta_generic_to_shared(p);
}
#define CP16(d, s)  asm volatile("cp.async.cg.shared.global [%0], [%1], 16;\n" :: "r"(d), "l"(s))
#define CPCOMMIT    asm volatile("cp.async.commit_group;\n")
#define CPWAIT1     asm volatile("cp.async.wait_group 1;\n")
#define CPWAIT0     asm volatile("cp.async.wait_group 0;\n")

// ---------------------------------------------------------------------------
// tf32 pre-round
// ---------------------------------------------------------------------------
__global__ void round_kernel(const float4* __restrict__ in, float4* __restrict__ out, int n4) {
    int i = blockIdx.x * 256 + threadIdx.x;
    if (i < n4) {
        float4 v = in[i];
        out[i] = make_float4(tf32f(v.x), tf32f(v.y), tf32f(v.z), tf32f(v.w));
    }
}

// ---------------------------------------------------------------------------
// QKV projection. Q scaled by 0.125*log2(e) (exp2-domain softmax).
// V stored transposed [B,H,Dh,S].
// ---------------------------------------------------------------------------
#define GP 36
#define GST (128*GP)

__global__ __launch_bounds__(256, 2) void qkv_kernel(const float* __restrict__ bias) {
    extern __shared__ float sm[];
    float* As = sm;
    float* Bs = sm + 2*GST;

    int tid = threadIdx.x;
    int m0 = blockIdx.y * 128, n0 = blockIdx.x * 128;
    int w = tid >> 5, lane = tid & 31;
    int wm = w >> 1, wn = w & 1;
    int g = lane >> 2, tg = lane & 3;
    int lr = tid >> 3, lc4 = (tid & 7) * 4;
    int l8 = lane & 7, b3 = (lane >> 3) & 1, b4 = lane >> 4;

    const float* X = g_X;
    const float* W = g_Wi;

    unsigned aA[2], aB[4];
#pragma unroll
    for (int mt = 0; mt < 2; mt++)
        aA[mt] = sptr(As) + ((wm*32 + mt*16 + l8 + b3*8) * GP + b4*4) * 4;
#pragma unroll
    for (int p = 0; p < 4; p++)
        aB[p] = sptr(Bs) + ((wn*64 + (2*p + b4)*8 + l8) * GP + b3*4) * 4;

#define QKV_ISSUE(kc, stg) do {                                               \
        _Pragma("unroll")                                                     \
        for (int p = 0; p < 4; p++) {                                         \
            int row = lr + p * 32;                                            \
            CP16(sptr(&As[(stg)*GST + row*GP + lc4]),                         \
                 X + (size_t)(m0 + row) * D_ + (kc) + lc4);                   \
            CP16(sptr(&Bs[(stg)*GST + row*GP + lc4]),                         \
                 W + (size_t)(n0 + row) * D_ + (kc) + lc4);                   \
        }                                                                     \
        CPCOMMIT;                                                             \
    } while (0)

    QKV_ISSUE(0, 0);

    float acc[2][8][4];
#pragma unroll
    for (int mt = 0; mt < 2; mt++)
#pragma unroll
        for (int nt = 0; nt < 8; nt++)
#pragma unroll
            for (int i = 0; i < 4; i++) acc[mt][nt][i] = 0.f;

    for (int kci = 0; kci < 16; kci++) {
        int cur = kci & 1;
        if (kci + 1 < 16) { QKV_ISSUE((kci + 1) * 32, cur ^ 1); CPWAIT1; }
        else              { CPWAIT0; }
        __syncthreads();
        unsigned sb = cur * (GST * 4);
#pragma unroll
        for (int ks = 0; ks < 4; ks++) {
            unsigned kbb = sb + ks * 32;
            unsigned a0[4], a1[4];
            ldsm4(a0, aA[0] + kbb);
            ldsm4(a1, aA[1] + kbb);
#pragma unroll
            for (int p = 0; p < 4; p++) {
                unsigned bb[4];
                ldsm4(bb, aB[p] + kbb);
                mma8(acc[0][2*p],   a0, bb);
                mma8(acc[1][2*p],   a1, bb);
                mma8(acc[0][2*p+1], a0, bb + 2);
                mma8(acc[1][2*p+1], a1, bb + 2);
            }
        }
        __syncthreads();
    }

    int sec = n0 >> 9;
    // Q gets 1/sqrt(Dh) * log2(e) so softmax can use pure ex2
    float qs = (sec == 0) ? 0.125f * 1.4426950408889634f : 1.0f;
#pragma unroll
    for (int mt = 0; mt < 2; mt++) {
#pragma unroll
        for (int half = 0; half < 2; half++) {
            int mm = m0 + wm * 32 + mt * 16 + g + half * 8;
            int bb = mm >> 11, ss = mm & (S_ - 1);
#pragma unroll
            for (int nt = 0; nt < 8; nt++) {
                int col = n0 + wn * 64 + nt * 8 + 2 * tg;
                float2 bi = *(const float2*)(bias + col);
                float v0 = tf32f((acc[mt][nt][half * 2 + 0] + bi.x) * qs);
                float v1 = tf32f((acc[mt][nt][half * 2 + 1] + bi.y) * qs);
                int d = col & (D_ - 1);
                int hh = d >> 6, dh = d & 63;
                if (sec < 2) {
                    float* dst = (sec == 0) ? g_Q : g_K;
                    float* p = dst + (((size_t)(bb * H_ + hh)) * S_ + ss) * DH_ + dh;
                    *(float2*)p = make_float2(v0, v1);
                } else {
                    // transposed V: [B,H,Dh,S]
                    float* pv = g_V + (((size_t)(bb * H_ + hh)) * DH_ + dh) * S_ + ss;
                    pv[0]  = v0;
                    pv[S_] = v1;
                }
            }
        }
    }
}

// ---------------------------------------------------------------------------
// Flash attention: all fragments via LDSM (Q, K, P, V). exp2-domain softmax.
// CTA = 128 q-rows, 128 threads. K pitch 68, V(transposed) pitch 68.
// ---------------------------------------------------------------------------
#define QP 68
#define KP 68
#define VP 68

__global__ __launch_bounds__(128, 2) void attn_kernel() {
    extern __shared__ float sm[];
    float* SP = sm;                  // 128 x 68 : Q, then P
    float* KB = sm + QT_ * QP;       // 64 x 68 (rows = key)
    float* VB = KB + 64 * KP;        // 64 x 68 (rows = d, cols = key)

    int qt = blockIdx.x, h = blockIdx.y, b = blockIdx.z;
    const float* Qg = g_Q + (((size_t)(b * H_ + h)) * S_ + qt * QT_) * DH_;
    const float* Kg = g_K + ((size_t)(b * H_ + h)) * S_ * DH_;
    const float* Vg = g_V + ((size_t)(b * H_ + h)) * DH_ * S_;

    int tid = threadIdx.x, w = tid >> 5, lane = tid & 31;
    int g = lane >> 2, tg = lane & 3;
    int l8 = lane & 7, b3 = (lane >> 3) & 1, b4 = lane >> 4;
    int r0 = w * 32;

    unsigned aSP[2], aK[4], aV[4];
#pragma unroll
    for (int f = 0; f < 2; f++)
        aSP[f] = sptr(SP) + ((r0 + f*16 + l8 + b3*8) * QP + b4*4) * 4;
#pragma unroll
    for (int p = 0; p < 4; p++) {
        aK[p] = sptr(KB) + (((2*p + b4)*8 + l8) * KP + b3*4) * 4;
        aV[p] = sptr(VB) + (((2*p + b4)*8 + l8) * VP + b3*4) * 4;
    }

    // prologue: Q -> SP ; K0 -> KB
#pragma unroll
    for (int p = 0; p < 16; p++) {
        int slot = tid + p * 128, row = slot >> 4, c4 = (slot & 15) * 4;
        CP16(sptr(&SP[row * QP + c4]), Qg + row * DH_ + c4);
    }
    CPCOMMIT;
#pragma unroll
    for (int p = 0; p < 8; p++) {
        int slot = tid + p * 128, row = slot >> 4, c4 = (slot & 15) * 4;
        CP16(sptr(&KB[row * KP + c4]), Kg + row * DH_ + c4);
    }
    CPCOMMIT;
    CPWAIT1;
    __syncthreads();

    unsigned qf[2][8][4];
#pragma unroll
    for (int f = 0; f < 2; f++)
#pragma unroll
        for (int ks = 0; ks < 8; ks++)
            ldsm4(qf[f][ks], aSP[f] + ks * 32);

    float oacc[2][8][4];
#pragma unroll
    for (int f = 0; f < 2; f++)
#pragma unroll
        for (int dt = 0; dt < 8; dt++)
#pragma unroll
            for (int i = 0; i < 4; i++) oacc[f][dt][i] = 0.f;
    float mrow[2][2], lrow[2][2];
#pragma unroll
    for (int f = 0; f < 2; f++) {
        mrow[f][0] = -CUDART_INF_F; mrow[f][1] = -CUDART_INF_F;
        lrow[f][0] = 0.f; lrow[f][1] = 0.f;
    }

    for (int kt = 0; kt < NT_; kt++) {
        // issue V[kt] (transposed: row = d, col = key)
        const float* Vt = Vg + (size_t)kt * 64;
#pragma unroll
        for (int p = 0; p < 8; p++) {
            int slot = tid + p * 128, row = slot >> 4, c4 = (slot & 15) * 4;
            CP16(sptr(&VB[row * VP + c4]), Vt + (size_t)row * S_ + c4);
        }
        CPCOMMIT;
        CPWAIT1;              // K[kt] ready (V in flight)
        __syncthreads();

        // S = Q K^T
        float s[2][8][4];
#pragma unroll
        for (int f = 0; f < 2; f++)
#pragma unroll
            for (int nt = 0; nt < 8; nt++)
#pragma unroll
                for (int i = 0; i < 4; i++) s[f][nt][i] = 0.f;
#pragma unroll
        for (int ks = 0; ks < 8; ks++) {
            unsigned kbb = ks * 32;
#pragma unroll
            for (int p = 0; p < 4; p++) {
                unsigned bb[4];
                ldsm4(bb, aK[p] + kbb);
                mma8(s[0][2*p],   qf[0][ks], bb);
                mma8(s[1][2*p],   qf[1][ks], bb);
                mma8(s[0][2*p+1], qf[0][ks], bb + 2);
                mma8(s[1][2*p+1], qf[1][ks], bb + 2);
            }
        }
        __syncthreads();      // KB free

        // prefetch K[kt+1]
        const float* Kt = Kg + (size_t)((kt + 1) & (NT_ - 1)) * 64 * DH_;
#pragma unroll
        for (int p = 0; p < 8; p++) {
            int slot = tid + p * 128, row = slot >> 4, c4 = (slot & 15) * 4;
            CP16(sptr(&KB[row * KP + c4]), Kt + row * DH_ + c4);
        }
        CPCOMMIT;

        // online softmax (exp2 domain — Q carries log2e)
#pragma unroll
        for (int f = 0; f < 2; f++) {
            float mxl = -CUDART_INF_F, mxh = -CUDART_INF_F;
#pragma unroll
            for (int nt = 0; nt < 8; nt++) {
                mxl = fmaxf(mxl, fmaxf(s[f][nt][0], s[f][nt][1]));
                mxh = fmaxf(mxh, fmaxf(s[f][nt][2], s[f][nt][3]));
            }
            mxl = fmaxf(mxl, __shfl_xor_sync(0xffffffffu, mxl, 1));
            mxl = fmaxf(mxl, __shfl_xor_sync(0xffffffffu, mxl, 2));
            mxh = fmaxf(mxh, __shfl_xor_sync(0xffffffffu, mxh, 1));
            mxh = fmaxf(mxh, __shfl_xor_sync(0xffffffffu, mxh, 2));
            float mnl = fmaxf(mrow[f][0], mxl), mnh = fmaxf(mrow[f][1], mxh);
            float al = ex2f(mrow[f][0] - mnl), ah = ex2f(mrow[f][1] - mnh);
            mrow[f][0] = mnl; mrow[f][1] = mnh;
            float rsl = 0.f, rsh = 0.f;
#pragma unroll
            for (int nt = 0; nt < 8; nt++) {
                s[f][nt][0] = ex2f(s[f][nt][0] - mnl);
                s[f][nt][1] = ex2f(s[f][nt][1] - mnl);
                s[f][nt][2] = ex2f(s[f][nt][2] - mnh);
                s[f][nt][3] = ex2f(s[f][nt][3] - mnh);
                rsl += s[f][nt][0] + s[f][nt][1];
                rsh += s[f][nt][2] + s[f][nt][3];
            }
            rsl += __shfl_xor_sync(0xffffffffu, rsl, 1);
            rsl += __shfl_xor_sync(0xffffffffu, rsl, 2);
            rsh += __shfl_xor_sync(0xffffffffu, rsh, 1);
            rsh += __shfl_xor_sync(0xffffffffu, rsh, 2);
            lrow[f][0] = lrow[f][0] * al + rsl;
            lrow[f][1] = lrow[f][1] * ah + rsh;
#pragma unroll
            for (int dt = 0; dt < 8; dt++) {
                oacc[f][dt][0] *= al; oacc[f][dt][1] *= al;
                oacc[f][dt][2] *= ah; oacc[f][dt][3] *= ah;
            }
            int rl = r0 + f * 16 + g, rh = rl + 8;
#pragma unroll
            for (int nt = 0; nt < 8; nt++) {
                int c = nt * 8 + 2 * tg;
                *(float2*)&SP[rl * QP + c] = make_float2(tf32f(s[f][nt][0]), tf32f(s[f][nt][1]));
                *(float2*)&SP[rh * QP + c] = make_float2(tf32f(s[f][nt][2]), tf32f(s[f][nt][3]));
            }
        }

        CPWAIT1;              // V[kt] ready (K[kt+1] in flight)
        __syncthreads();

        // O += P V : LDSM for P and V
#pragma unroll
        for (int ks = 0; ks < 8; ks++) {
            unsigned kbb = ks * 32;
            unsigned pa[2][4];
            ldsm4(pa[0], aSP[0] + kbb);
            ldsm4(pa[1], aSP[1] + kbb);
#pragma unroll
            for (int p = 0; p < 4; p++) {
                unsigned vb[4];
                ldsm4(vb, aV[p] + kbb);
                mma8(oacc[0][2*p],   pa[0], vb);
                mma8(oacc[1][2*p],   pa[1], vb);
                mma8(oacc[0][2*p+1], pa[0], vb + 2);
                mma8(oacc[1][2*p+1], pa[1], vb + 2);
            }
        }
        __syncthreads();      // VB free before next V issue
    }

    // epilogue
    float* Og = g_O + ((size_t)(b * S_ + qt * QT_)) * D_ + h * DH_;
#pragma unroll
    for (int f = 0; f < 2; f++) {
        float il = 1.0f / lrow[f][0], ih = 1.0f / lrow[f][1];
        int rl = r0 + f * 16 + g, rh = rl + 8;
#pragma unroll
        for (int dt = 0; dt < 8; dt++) {
            int c = dt * 8 + 2 * tg;
            *(float2*)&Og[(size_t)rl * D_ + c] =
                make_float2(tf32f(oacc[f][dt][0] * il), tf32f(oacc[f][dt][1] * il));
            *(float2*)&Og[(size_t)rh * D_ + c] =
                make_float2(tf32f(oacc[f][dt][2] * ih), tf32f(oacc[f][dt][3] * ih));
        }
    }
}

// ---------------------------------------------------------------------------
// Output projection
// ---------------------------------------------------------------------------
__global__ __launch_bounds__(256, 2) void out_kernel(const float* __restrict__ bias,
                                                     float* __restrict__ out) {
    extern __shared__ float sm[];
    float* As = sm;
    float* Bs = sm + 2*GST;

    int tid = threadIdx.x;
    int m0 = blockIdx.y * 128, n0 = blockIdx.x * 128;
    int w = tid >> 5, lane = tid & 31;
    int wm = w >> 1, wn = w & 1;
    int g = lane >> 2, tg = lane & 3;
    int lr = tid >> 3, lc4 = (tid & 7) * 4;
    int l8 = lane & 7, b3 = (lane >> 3) & 1, b4 = lane >> 4;

    const float* X = g_O;
    const float* W = g_Wo;

    unsigned aA[2], aB[4];
#pragma unroll
    for (int mt = 0; mt < 2; mt++)
        aA[mt] = sptr(As) + ((wm*32 + mt*16 + l8 + b3*8) * GP + b4*4) * 4;
#pragma unroll
    for (int p = 0; p < 4; p++)
        aB[p] = sptr(Bs) + ((wn*64 + (2*p + b4)*8 + l8) * GP + b3*4) * 4;

#define OUT_ISSUE(kc, stg) do {                                               \
        _Pragma("unroll")                                                     \
        for (int p = 0; p < 4; p++) {                                         \
            int row = lr + p * 32;                                            \
            CP16(sptr(&As[(stg)*GST + row*GP + lc4]),                         \
                 X + (size_t)(m0 + row) * D_ + (kc) + lc4);                   \
            CP16(sptr(&Bs[(stg)*GST + row*GP + lc4]),                         \
                 W + (size_t)(n0 + row) * D_ + (kc) + lc4);                   \
        }                                                                     \
        CPCOMMIT;                                                             \
    } while (0)

    OUT_ISSUE(0, 0);

    float acc[2][8][4];
#pragma unroll
    for (int mt = 0; mt < 2; mt++)
#pragma unroll
        for (int nt = 0; nt < 8; nt++)
#pragma unroll
            for (int i = 0; i < 4; i++) acc[mt][nt][i] = 0.f;

    for (int kci = 0; kci < 16; kci++) {
        int cur = kci & 1;
        if (kci + 1 < 16) { OUT_ISSUE((kci + 1) * 32, cur ^ 1); CPWAIT1; }
        else              { CPWAIT0; }
        __syncthreads();
        unsigned sb = cur * (GST * 4);
#pragma unroll
        for (int ks = 0; ks < 4; ks++) {
            unsigned kbb = sb + ks * 32;
            unsigned a0[4], a1[4];
            ldsm4(a0, aA[0] + kbb);
            ldsm4(a1, aA[1] + kbb);
#pragma unroll
            for (int p = 0; p < 4; p++) {
                unsigned bb[4];
                ldsm4(bb, aB[p] + kbb);
                mma8(acc[0][2*p],   a0, bb);
                mma8(acc[1][2*p],   a1, bb);
                mma8(acc[0][2*p+1], a0, bb + 2);
                mma8(acc[1][2*p+1], a1, bb + 2);
            }
        }
        __syncthreads();
    }

#pragma unroll
    for (int mt = 0; mt < 2; mt++) {
#pragma unroll
        for (int half = 0; half < 2; half++) {
            int mm = m0 + wm * 32 + mt * 16 + g + half * 8;
#pragma unroll
            for (int nt = 0; nt < 8; nt++) {
                int col = n0 + wn * 64 + nt * 8 + 2 * tg;
                float2 bi = *(const float2*)(bias + col);
                *(float2*)&out[(size_t)mm * D_ + col] =
                    make_float2(acc[mt][nt][half * 2 + 0] + bi.x,
                                acc[mt][nt][half * 2 + 1] + bi.y);
            }
        }
    }
}

// ---------------------------------------------------------------------------
extern "C" void kernel_launch(void* const* d_in, const int* in_sizes, int n_in,
                              void* d_out, int out_size) {
    const float* x     = (const float*)d_in[0];
    const float* w_in  = (const float*)d_in[1];
    const float* b_in  = (const float*)d_in[2];
    const float* w_out = (const float*)d_in[3];
    const float* b_out = (const float*)d_in[4];
    float* out = (float*)d_out;

    const int gemm_smem = 4 * GST * 4;                          // 73728 B
    const int attn_smem = (QT_*QP + 64*KP + 64*VP) * 4;         // 69632 B
    cudaFuncSetAttribute(qkv_kernel,  cudaFuncAttributeMaxDynamicSharedMemorySize, gemm_smem);
    cudaFuncSetAttribute(out_kernel,  cudaFuncAttributeMaxDynamicSharedMemorySize, gemm_smem);
    cudaFuncSetAttribute(attn_kernel, cudaFuncAttributeMaxDynamicSharedMemorySize, attn_smem);

    float* gx;  cudaGetSymbolAddress((void**)&gx,  g_X);
    float* gwi; cudaGetSymbolAddress((void**)&gwi, g_Wi);
    float* gwo; cudaGetSymbolAddress((void**)&gwo, g_Wo);
    round_kernel<<<(M_*D_/4 + 255)/256, 256>>>((const float4*)x,     (float4*)gx,  M_*D_/4);
    round_kernel<<<(3*D_*D_/4 + 255)/256, 256>>>((const float4*)w_in,  (float4*)gwi, 3*D_*D_/4);
    round_kernel<<<(D_*D_/4 + 255)/256, 256>>>((const float4*)w_out, (float4*)gwo, D_*D_/4);

    qkv_kernel<<<dim3(12, 128), 256, gemm_smem>>>(b_in);
    attn_kernel<<<dim3(S_ / QT_, H_, B_), 128, attn_smem>>>();
    out_kernel<<<dim3(4, 128), 256, gemm_smem>>>(b_out, out);
}